// round 6
// baseline (speedup 1.0000x reference)
#include <cuda_runtime.h>
#include <cuda_bf16.h>
#include <cstdint>

// PairExcludeMask: out[f,i,n] = type_mask[ atype[f,i]*9 + tj ]
//   tj = (nlist[f,i,n] == -1) ? 8 : atype[f, nlist[f,i,n]]
//
// pack_kernel: per atom j, byte B[j] whose bit ti = (type_mask[ti*9+type_j] != 0).
// mask_kernel: per-frame 32KB byte table in smem. One warp per row ->
// warp-uniform center type ti -> m = 1<<ti. Rows that pass/fail every type
// are written as constants without touching nlist. Slow path per neighbor:
//   LDS.U8 B[j]; (B & m) ? 1.0f : 0.0f  -- no second table lookup.

static constexpr int NF     = 4;
static constexpr int NLOC   = 16384;
static constexpr int NNEI   = 128;
static constexpr int NALL   = 32768;
static constexpr int NTYPES = 8;
static constexpr int TM1    = NTYPES + 1;          // 9
static constexpr uint32_t FULL = (1u << TM1) - 1;  // 0x1FF
static constexpr uint32_t ONEF = 0x3F800000u;      // 1.0f bits

static constexpr int TBL_BYTES = NALL + 16;        // + virtual atom + pad

__device__ __align__(16) uint8_t g_byte[NF][TBL_BYTES];

// ---------------- kernel 1: per-atom mask byte ----------------
__global__ __launch_bounds__(256)
void pack_kernel(const int* __restrict__ atype, const float* __restrict__ tmask)
{
    __shared__ uint32_t s_tb[16];                  // per-type mask byte
    if (threadIdx.x < TM1) {
        uint32_t b = 0;
        #pragma unroll
        for (int ti = 0; ti < NTYPES; ++ti)        // centers have ti < 8
            b |= (tmask[ti * TM1 + threadIdx.x] != 0.0f ? 1u : 0u) << ti;
        s_tb[threadIdx.x] = b;
    }
    __syncthreads();

    const int idx = blockIdx.x * 256 + threadIdx.x;   // over NF*NALL/16
    const int f   = idx >> 11;                        // / (NALL/16)
    const int wi  = idx & (NALL / 16 - 1);
    const int4* __restrict__ at4 = (const int4*)(atype + f * NALL);

    uint4 o;
    uint32_t* po = &o.x;
    #pragma unroll
    for (int q = 0; q < 4; ++q) {
        int4 a = at4[wi * 4 + q];
        po[q] = s_tb[a.x] | (s_tb[a.y] << 8) | (s_tb[a.z] << 16) | (s_tb[a.w] << 24);
    }
    ((uint4*)g_byte[f])[wi] = o;

    if (wi == 0) {                                 // virtual atom j == NALL
        uint32_t v = s_tb[NTYPES];                 // byte for type 8 neighbors
        #pragma unroll
        for (int k = 0; k < 16; ++k)
            g_byte[f][NALL + k] = (uint8_t)(k == 0 ? v : 0);
    }
}

// ---------------- kernel 2: stream the mask ----------------
static constexpr int THREADS_B = 256;
static constexpr int BPF       = 128;                      // blocks per frame
static constexpr int ROWS_PB   = NLOC / BPF;               // 128 rows / block
static constexpr int ROW_VEC   = NNEI / 4;                 // 32 vec4 per row
static constexpr int VEC_PB    = ROWS_PB * ROW_VEC;        // 4096
static constexpr int BATCH     = 4;
static constexpr int NBATCH    = VEC_PB / (THREADS_B * BATCH);  // 4
static constexpr int BLOCKS_B  = NF * BPF;                 // 512 (single wave)

__global__ __launch_bounds__(THREADS_B)
void mask_kernel(const int4* __restrict__ nlist4,
                 const int*  __restrict__ atype,
                 const float* __restrict__ tmask,
                 uint4* __restrict__ out4)
{
    __shared__ uint8_t  s_byte[TBL_BYTES];         // 32.8 KB mask-byte table
    __shared__ uint32_t s_rw[16];                  // per-type 9-bit row word
    __shared__ uint32_t s_rowinfo[ROWS_PB];        // (flag<<16) | (1<<ti)

    const int tid  = threadIdx.x;
    const int f    = blockIdx.x >> 7;              // / BPF
    const int row0 = (blockIdx.x & (BPF - 1)) * ROWS_PB;

    // coalesced 16B copy of the byte table from L2
    {
        const uint4* __restrict__ src = (const uint4*)g_byte[f];
        uint4* dst = (uint4*)s_byte;
        #pragma unroll
        for (int k = tid; k < TBL_BYTES / 16; k += THREADS_B)
            dst[k] = src[k];
    }
    if (tid < TM1) {
        uint32_t w = 0;
        #pragma unroll
        for (int tj = 0; tj < TM1; ++tj)
            w |= (tmask[tid * TM1 + tj] != 0.0f ? 1u : 0u) << tj;
        s_rw[tid] = w;
    }
    __syncthreads();
    if (tid < ROWS_PB) {
        const int ti = __ldg(atype + f * NALL + row0 + tid);
        const uint32_t rw = s_rw[ti];
        const uint32_t flag = (rw == FULL) ? 1u : ((rw == 0u) ? 0u : 2u);
        s_rowinfo[tid] = (flag << 16) | (1u << ti);
    }
    __syncthreads();

    const size_t base = ((size_t)f * NLOC + row0) * ROW_VEC;
    const int4*  __restrict__ nl = nlist4 + base;
    uint4*       __restrict__ ob = out4  + base;

    #pragma unroll
    for (int b = 0; b < NBATCH; ++b) {
        uint32_t info[BATCH];
        int4     nj[BATCH];

        #pragma unroll
        for (int k = 0; k < BATCH; ++k)
            info[k] = s_rowinfo[(tid + (b * BATCH + k) * THREADS_B) >> 5];

        #pragma unroll
        for (int k = 0; k < BATCH; ++k)
            if ((info[k] >> 16) == 2u)
                nj[k] = nl[tid + (b * BATCH + k) * THREADS_B];

        #pragma unroll
        for (int k = 0; k < BATCH; ++k) {
            const int v = tid + (b * BATCH + k) * THREADS_B;
            const uint32_t flag = info[k] >> 16;

            if (flag == 1u) { ob[v] = make_uint4(ONEF, ONEF, ONEF, ONEF); continue; }
            if (flag == 0u) { ob[v] = make_uint4(0u, 0u, 0u, 0u);         continue; }

            const uint32_t m = info[k] & 0xFFFFu;  // 1 << ti (warp-uniform)

            uint32_t j0 = min((uint32_t)nj[k].x, (uint32_t)NALL);
            uint32_t j1 = min((uint32_t)nj[k].y, (uint32_t)NALL);
            uint32_t j2 = min((uint32_t)nj[k].z, (uint32_t)NALL);
            uint32_t j3 = min((uint32_t)nj[k].w, (uint32_t)NALL);

            uint32_t b0 = s_byte[j0];
            uint32_t b1 = s_byte[j1];
            uint32_t b2 = s_byte[j2];
            uint32_t b3 = s_byte[j3];

            uint4 r;
            r.x = (b0 & m) ? ONEF : 0u;
            r.y = (b1 & m) ? ONEF : 0u;
            r.z = (b2 & m) ? ONEF : 0u;
            r.w = (b3 & m) ? ONEF : 0u;

            ob[v] = r;
        }
    }
}

extern "C" void kernel_launch(void* const* d_in, const int* in_sizes, int n_in,
                              void* d_out, int out_size)
{
    const int4*  nlist4 = (const int4*) d_in[0];
    const int*   atype  = (const int*)  d_in[1];
    const float* tmask  = (const float*)d_in[2];
    // d_in[3] = ntypes scalar (8, baked into constants)

    uint4* out4 = (uint4*)d_out;

    pack_kernel<<<NF * NALL / 16 / 256, 256>>>(atype, tmask);
    mask_kernel<<<BLOCKS_B, THREADS_B>>>(nlist4, atype, tmask, out4);
}